// round 16
// baseline (speedup 1.0000x reference)
#include <cuda_runtime.h>
#include <math.h>

#define Bsz 64
#define Pn  2048
#define Ln  512
#define Hn  8
#define NC  16      // row-chunks per batch in flash pass
#define RPB (Pn/NC) // 128 rows per flash block
#define TR  8       // rows per smem stage

// k4 smem layout (bytes): x stages 2*16512, gu 16512, cf 2*256, scl 2*32
#define XROW  2064              // padded row stride (bank offset 4 per row)
#define XSTG  (TR*XROW)         // 16512
#define OFF_GU  (2*XSTG)        // 33024
#define OFF_CF  (OFF_GU + Hn*XROW)   // 49536
#define OFF_SCL (OFF_CF + 2*64*4)    // 50048
#define SMEM_K4 (OFF_SCL + 2*8*4)    // 50112

typedef unsigned long long u64;

// ---------------- static scratch (no allocation) ----------------
__device__ float  g_qn [Bsz*Ln];
__device__ float  g_Q  [Bsz*Ln];
__device__ __align__(16) float g_gu [Bsz*Hn*Ln];
__device__ float  g_Sgu[Bsz*Hn];
__device__ float  g_bu [Bsz*Hn];
__device__ float4 g_A4 [(size_t)Bsz*NC*Hn*(Ln/4)];   // partial accumulators
__device__ float4 g_msb[Bsz*NC*Hn];                  // (M, S, c, 0) per partial

// ---------------- packed f32x2 helpers ----------------
__device__ __forceinline__ u64 pk2(float lo, float hi) {
    u64 r; asm("mov.b64 %0, {%1,%2};" : "=l"(r) : "f"(lo), "f"(hi)); return r;
}
__device__ __forceinline__ void upk2(u64 v, float& lo, float& hi) {
    asm("mov.b64 {%0,%1}, %2;" : "=f"(lo), "=f"(hi) : "l"(v));
}
__device__ __forceinline__ u64 fma2(u64 a, u64 b, u64 c) {
    u64 r; asm("fma.rn.f32x2 %0, %1, %2, %3;" : "=l"(r) : "l"(a), "l"(b), "l"(c)); return r;
}
__device__ __forceinline__ u64 mul2(u64 a, u64 b) {
    u64 r; asm("mul.rn.f32x2 %0, %1, %2;" : "=l"(r) : "l"(a), "l"(b)); return r;
}
__device__ __forceinline__ u64 add2(u64 a, u64 b) {
    u64 r; asm("add.rn.f32x2 %0, %1, %2;" : "=l"(r) : "l"(a), "l"(b)); return r;
}

// ---------------- cp.async helpers ----------------
__device__ __forceinline__ void cpasync16(void* smem, const void* g) {
    unsigned s = (unsigned)__cvta_generic_to_shared(smem);
    asm volatile("cp.async.cg.shared.global [%0], [%1], 16;" :: "r"(s), "l"(g));
}
#define CP_COMMIT()  asm volatile("cp.async.commit_group;")
#define CP_WAIT(N)   asm volatile("cp.async.wait_group %0;" :: "n"(N))

// ---------------- K1: LN of query rows + init ----------------
__global__ void k1_ln_init(const float* __restrict__ xt,
                           const float* __restrict__ g, const float* __restrict__ b_,
                           const float* __restrict__ resb, float* __restrict__ outctx)
{
    int b = blockIdx.x, t = threadIdx.x;
    __shared__ float xs[Ln];
    __shared__ float red[16];
    __shared__ float stats[2];
    float2 v = ((const float2*)xt)[b*(Ln/2) + t];
    xs[2*t] = v.x; xs[2*t+1] = v.y;
    float s1 = v.x + v.y, s2 = v.x*v.x + v.y*v.y;
    #pragma unroll
    for (int o = 16; o; o >>= 1) {
        s1 += __shfl_xor_sync(~0u, s1, o);
        s2 += __shfl_xor_sync(~0u, s2, o);
    }
    int w = t >> 5, lane = t & 31;
    if (!lane) { red[w] = s1; red[8+w] = s2; }
    __syncthreads();
    if (!t) {
        float a = 0.f, c = 0.f;
        #pragma unroll
        for (int i = 0; i < 8; i++) { a += red[i]; c += red[8+i]; }
        float mean = a * (1.f/Ln);
        float var  = c * (1.f/Ln) - mean*mean;
        stats[0] = mean; stats[1] = rsqrtf(var + 1e-5f);
    }
    __syncthreads();
    float mean = stats[0], rstd = stats[1];
    #pragma unroll
    for (int l = t; l < Ln; l += 256) {
        g_qn[b*Ln + l]   = (xs[l] - mean) * rstd * g[l] + b_[l];
        outctx[b*Ln + l] = resb[l];
        g_Q[b*Ln + l]    = 0.f;
    }
    if (t < 8) { g_Sgu[b*8 + t] = 0.f; g_bu[b*8 + t] = 0.f; }
}

// ---------------- K2: split-K GEMMs (32-wide K chunks, 256 blocks) ----------------
__global__ void k2_gemm(const float* __restrict__ xt,
                        const float* __restrict__ Wq, const float* __restrict__ Wr,
                        float* __restrict__ outctx)
{
    int kc = blockIdx.x, bg = blockIdx.y, mat = blockIdx.z;
    const float* X = mat ? xt : g_qn;
    const float* W = mat ? Wr : Wq;
    float* OUT     = mat ? outctx : g_Q;
    __shared__ float xsm[8*32];
    int t = threadIdx.x;
    xsm[t] = X[(bg*8 + (t>>5))*Ln + kc*32 + (t&31)];   // 256 threads = 8 rows x 32 cols
    __syncthreads();
    float acc[16];
    #pragma unroll
    for (int i = 0; i < 16; i++) acc[i] = 0.f;
    int d0 = t, d1 = t + 256;
    #pragma unroll 4
    for (int kk = 0; kk < 32; kk++) {
        float w0 = W[(kc*32 + kk)*Ln + d0];
        float w1 = W[(kc*32 + kk)*Ln + d1];
        #pragma unroll
        for (int bb = 0; bb < 8; bb++) {
            float x = xsm[bb*32 + kk];
            acc[2*bb]   += x * w0;
            acc[2*bb+1] += x * w1;
        }
    }
    #pragma unroll
    for (int bb = 0; bb < 8; bb++) {
        atomicAdd(&OUT[(bg*8+bb)*Ln + d0], acc[2*bb]);
        atomicAdd(&OUT[(bg*8+bb)*Ln + d1], acc[2*bb+1]);
    }
}

// ---------------- K3: tiled mini-GEMM  u[b,h,l] = (1/8) Wk_row(l,head h) . Q(b,head h) ----------------
__global__ void k3_u(const float* __restrict__ Wk,
                     const float* __restrict__ lng, const float* __restrict__ lnb)
{
    int lt = blockIdx.x, bg = blockIdx.y;
    int l0 = lt*16, b0 = bg*4;
    int t = threadIdx.x;
    int l = t & 15, h = t >> 4;
    __shared__ float4 Wks[16*128];
    __shared__ float4 Qs [4*128];

    const float4* wsrc = (const float4*)(Wk + (size_t)l0*Ln);
    #pragma unroll
    for (int k = 0; k < 16; k++) Wks[t + k*128] = wsrc[t + k*128];
    const float4* qsrc = (const float4*)(g_Q + (size_t)b0*Ln);
    #pragma unroll
    for (int k = 0; k < 4; k++) Qs[t + k*128] = qsrc[t + k*128];
    __syncthreads();

    float4 wr[16];
    #pragma unroll
    for (int k = 0; k < 16; k++) wr[k] = Wks[l*128 + h*16 + k];

    float gl = lng[l0 + l], bl = lnb[l0 + l];

    #pragma unroll
    for (int bb = 0; bb < 4; bb++) {
        float4 a4 = make_float4(0.f, 0.f, 0.f, 0.f);
        #pragma unroll
        for (int k = 0; k < 16; k++) {
            float4 q = Qs[bb*128 + h*16 + k];
            a4.x = fmaf(wr[k].x, q.x, a4.x);
            a4.y = fmaf(wr[k].y, q.y, a4.y);
            a4.z = fmaf(wr[k].z, q.z, a4.z);
            a4.w = fmaf(wr[k].w, q.w, a4.w);
        }
        float acc = (a4.x + a4.y) + (a4.z + a4.w);
        float u = acc * 0.125f;
        float guv = gl * u;
        g_gu[((size_t)(b0+bb)*Hn + h)*Ln + l0 + l] = guv;
        float sS = guv, sB = bl * u;
        #pragma unroll
        for (int o = 8; o; o >>= 1) {
            sS += __shfl_xor_sync(~0u, sS, o);
            sB += __shfl_xor_sync(~0u, sB, o);
        }
        if (l == 0) {
            atomicAdd(&g_Sgu[(b0+bb)*Hn + h], sS);
            atomicAdd(&g_bu [(b0+bb)*Hn + h], sB);
        }
    }
}

// ---------------- K4: warp-specialized flash, software-pipelined A-loop ----------------
// A-warps (vw 0,1): lane = (head_local, row); full-row fused dot+stats, no hot shuffles.
// B-warps (vw 2,3): 256-col slice, 8-head register accumulators + cp.async pipeline.
__global__ void __launch_bounds__(128, 4) k4_flash(
    const float* __restrict__ xd, float* __restrict__ attn_scores)
{
    extern __shared__ char sm[];
    int b = blockIdx.x, chunk = blockIdx.y;
    int t = threadIdx.x, w = t >> 5, lane = t & 31;
    int vw = (w + b + chunk) & 3;          // rotate roles across SMSPs
    const size_t rowbase = (size_t)b*Pn + (size_t)chunk*RPB;

    // ---- prologue: stage gu + x tile 0 ----
    {
        const char* gsrc = (const char*)(g_gu + (size_t)b*Hn*Ln);
        #pragma unroll
        for (int c = 0; c < 8; c++) {
            int idx = t + c*128;                  // 1024 chunks of 16B
            int h = idx >> 7, j = idx & 127;
            cpasync16(sm + OFF_GU + h*XROW + j*16, gsrc + idx*16);
        }
        const char* xsrc = (const char*)(xd + rowbase*Ln);
        #pragma unroll
        for (int c = 0; c < 8; c++) {
            int idx = t + c*128;
            int r = idx >> 7, j = idx & 127;
            cpasync16(sm + r*XROW + j*16, xsrc + idx*16);
        }
        CP_COMMIT();
        CP_WAIT(0);
    }

    // ---- per-role state ----
    int hl = lane >> 3, r = lane & 7;
    int h  = (vw & 1)*4 + hl;              // A: this lane's head
    int bw = vw - 2;                       // B: col-slice id (0/1)
    float Sgu_h = 0.f, bu_h = 0.f;
    const char* gurow = sm + OFF_GU + h*XROW;
    float* scout = attn_scores + ((size_t)b*Hn + h)*Pn + chunk*RPB;
    if (vw < 2) {
        Sgu_h = g_Sgu[b*Hn + h];
        bu_h  = g_bu [b*Hn + h];
    }
    float M = -1e30f, Sp = 0.f, cpart = 0.f;
    u64 acc[8][4];
    #pragma unroll
    for (int i = 0; i < 8; i++) { acc[i][0]=0ull; acc[i][1]=0ull; acc[i][2]=0ull; acc[i][3]=0ull; }

    __syncthreads();

    // ---- main loop: A computes tile T, B accumulates tile T-1, loads T+1 ----
    for (int T = 0; T <= 16; T++) {
        if (vw >= 2) CP_WAIT(0);           // B's own group for x[T] (if any)
        __syncthreads();                   // x[T] + cf[T-1] visible to all

        if (vw < 2) {
            if (T < 16) {
                const ulonglong2* xp = (const ulonglong2*)(sm + (T&1)*XSTG + r*XROW);
                const ulonglong2* gp = (const ulonglong2*)gurow;
                u64 d0=0ull,d1=0ull,s1a=0ull,s1b=0ull,s2a=0ull,s2b=0ull;
                // explicit software pipeline: load group g+1 before math of group g
                ulonglong2 xv[4], gv[4];
                #pragma unroll
                for (int k = 0; k < 4; k++) { xv[k] = xp[k]; gv[k] = gp[k]; }
                #pragma unroll 8
                for (int g = 0; g < 32; g++) {
                    ulonglong2 xn[4], gn[4];
                    int nb = (g + 1 < 32) ? (g + 1)*4 : 0;
                    #pragma unroll
                    for (int k = 0; k < 4; k++) { xn[k] = xp[nb + k]; gn[k] = gp[nb + k]; }
                    #pragma unroll
                    for (int k = 0; k < 4; k++) {
                        d0  = fma2(xv[k].x, gv[k].x, d0);
                        d1  = fma2(xv[k].y, gv[k].y, d1);
                        s1a = add2(s1a, xv[k].x);
                        s1b = add2(s1b, xv[k].y);
                        s2a = fma2(xv[k].x, xv[k].x, s2a);
                        s2b = fma2(xv[k].y, xv[k].y, s2b);
                    }
                    #pragma unroll
                    for (int k = 0; k < 4; k++) { xv[k] = xn[k]; gv[k] = gn[k]; }
                }
                float lo, hi;
                upk2(add2(d0,d1),   lo, hi); float dsum = lo + hi;
                upk2(add2(s1a,s1b), lo, hi); float s1 = lo + hi;
                upk2(add2(s2a,s2b), lo, hi); float s2 = lo + hi;
                float mean = s1 * (1.f/Ln);
                float var  = s2 * (1.f/Ln) - mean*mean;
                float rstd = rsqrtf(var + 1e-5f);
                float score = rstd*(dsum - mean*Sgu_h) + bu_h;
                // max over the 8 rows of this head (3 shuffles, group-local)
                float m = score;
                m = fmaxf(m, __shfl_xor_sync(~0u, m, 1));
                m = fmaxf(m, __shfl_xor_sync(~0u, m, 2));
                m = fmaxf(m, __shfl_xor_sync(~0u, m, 4));
                float nM  = fmaxf(M, m);
                float scl = __expf(M - nM);
                float e   = __expf(score - nM);
                Sp = Sp*scl + e;
                float cfv = e * rstd;
                cpart = cpart*scl + cfv*mean;
                M = nM;
                ((float*)(sm + OFF_CF))[(T&1)*64 + h*8 + r] = cfv;
                if (r == 0) ((float*)(sm + OFF_SCL))[(T&1)*8 + h] = scl;
                scout[T*TR + r] = score;
            }
        } else {
            if (T >= 1) {
                int pm = (T-1) & 1;
                const float* cfp  = (const float*)(sm + OFF_CF) + pm*64;
                const float* sclp = (const float*)(sm + OFF_SCL) + pm*8;
                #pragma unroll
                for (int hh = 0; hh < 8; hh++) {
                    float sv = sclp[hh];
                    u64 s2v = pk2(sv, sv);
                    acc[hh][0]=mul2(acc[hh][0],s2v); acc[hh][1]=mul2(acc[hh][1],s2v);
                    acc[hh][2]=mul2(acc[hh][2],s2v); acc[hh][3]=mul2(acc[hh][3],s2v);
                }
                const char* xr0 = sm + pm*XSTG + bw*1024 + lane*32;
                #pragma unroll
                for (int rr = 0; rr < 8; rr++) {
                    ulonglong2 xa = *(const ulonglong2*)(xr0 + rr*XROW);
                    ulonglong2 xb = *(const ulonglong2*)(xr0 + rr*XROW + 16);
                    #pragma unroll
                    for (int hh = 0; hh < 8; hh++) {
                        float cfv = cfp[hh*8 + rr];
                        u64 c2 = pk2(cfv, cfv);
                        acc[hh][0] = fma2(c2, xa.x, acc[hh][0]);
                        acc[hh][1] = fma2(c2, xa.y, acc[hh][1]);
                        acc[hh][2] = fma2(c2, xb.x, acc[hh][2]);
                        acc[hh][3] = fma2(c2, xb.y, acc[hh][3]);
                    }
                }
            }
            if (T + 1 < 16) {   // load x[T+1] into slot (T+1)&1 (just freed by this warp)
                const char* xsrc = (const char*)(xd + (rowbase + (size_t)(T+1)*TR)*Ln);
                char* dst = sm + ((T+1)&1)*XSTG + bw*1024 + lane*32;
                #pragma unroll
                for (int rr = 0; rr < 8; rr++) {
                    cpasync16(dst + rr*XROW,      xsrc + rr*2048 + bw*1024 + lane*32);
                    cpasync16(dst + rr*XROW + 16, xsrc + rr*2048 + bw*1024 + lane*32 + 16);
                }
                CP_COMMIT();
            }
        }
    }

    // ---- epilogue ----
    if (vw < 2) {
        float a0 = Sp, a1 = cpart;
        a0 += __shfl_xor_sync(~0u, a0, 1); a1 += __shfl_xor_sync(~0u, a1, 1);
        a0 += __shfl_xor_sync(~0u, a0, 2); a1 += __shfl_xor_sync(~0u, a1, 2);
        a0 += __shfl_xor_sync(~0u, a0, 4); a1 += __shfl_xor_sync(~0u, a1, 4);
        if (r == 0)
            g_msb[(b*NC + chunk)*Hn + h] = make_float4(M, a0, a1, 0.f);
    } else {
        size_t base = ((size_t)(b*NC + chunk)*Hn)*(Ln/4);
        #pragma unroll
        for (int hh = 0; hh < 8; hh++) {
            ulonglong2 v0; v0.x = acc[hh][0]; v0.y = acc[hh][1];
            ulonglong2 v1; v1.x = acc[hh][2]; v1.y = acc[hh][3];
            ulonglong2* dst = (ulonglong2*)&g_A4[base + (size_t)hh*(Ln/4) + bw*64 + lane*2];
            dst[0] = v0; dst[1] = v1;
        }
    }
}

// ---------------- K5: combine partials, ctx GEMV (ldg), AND normalize attn ----------------
__global__ void k5_reduce(const float* __restrict__ Wv,
                          const float* __restrict__ lng, const float* __restrict__ lnb,
                          float* __restrict__ outctx, float* __restrict__ attn)
{
    int b = blockIdx.x, h = blockIdx.y;
    int t = threadIdx.x;   // 128 threads
    __shared__ float wsh[NC];
    __shared__ float sInvS, sC, sMg;
    __shared__ float ws[Ln];
    __shared__ float part[128];
    if (t < 32) {          // parallel combine of the 16 partials (warp 0)
        int i = t & 15;
        float4 m = g_msb[(b*NC + i)*Hn + h];
        float Mg = m.x;
        #pragma unroll
        for (int o = 1; o < 16; o <<= 1) Mg = fmaxf(Mg, __shfl_xor_sync(~0u, Mg, o));
        Mg = fmaxf(Mg, __shfl_xor_sync(~0u, Mg, 16));   // full-warp uniform
        float wgt = __expf(m.x - Mg);
        if (t < 16) wsh[i] = wgt;
        float sg = wgt*m.y, cg = wgt*m.z;
        #pragma unroll
        for (int o = 1; o < 16; o <<= 1) {
            sg += __shfl_xor_sync(~0u, sg, o);
            cg += __shfl_xor_sync(~0u, cg, o);
        }
        if (t == 0) { sInvS = 1.f/sg; sC = cg; sMg = Mg; }
    }
    __syncthreads();
    float invS = sInvS, cg = sC, Mg = sMg;
    {
        int v = t;
        float4 acc = make_float4(0.f, 0.f, 0.f, 0.f);
        for (int i = 0; i < NC; i++) {
            float4 a = g_A4[((size_t)(b*NC+i)*Hn + h)*(Ln/4) + v];
            float wgt = wsh[i];
            acc.x += wgt*a.x; acc.y += wgt*a.y; acc.z += wgt*a.z; acc.w += wgt*a.w;
        }
        float4 g4 = ((const float4*)lng)[v], b4 = ((const float4*)lnb)[v];
        ws[4*v+0] = g4.x*(acc.x - cg)*invS + b4.x;
        ws[4*v+1] = g4.y*(acc.y - cg)*invS + b4.y;
        ws[4*v+2] = g4.z*(acc.z - cg)*invS + b4.z;
        ws[4*v+3] = g4.w*(acc.w - cg)*invS + b4.w;
    }
    __syncthreads();
    int d = t & 63, half = t >> 6;
    float acc = 0.f;
    #pragma unroll 8
    for (int l = half*256; l < half*256 + 256; l++)
        acc += ws[l] * __ldg(&Wv[l*Ln + h*64 + d]);
    part[t] = acc;
    __syncthreads();
    if (t < 64) outctx[b*Ln + h*64 + t] += part[t] + part[64 + t];

    float4* astr = (float4*)(attn + ((size_t)(b*Hn) + h)*Pn);
    #pragma unroll
    for (int rep = 0; rep < 4; rep++) {
        int i = t + rep*128;
        float4 s = astr[i];
        s.x = __expf(s.x - Mg)*invS;
        s.y = __expf(s.y - Mg)*invS;
        s.z = __expf(s.z - Mg)*invS;
        s.w = __expf(s.w - Mg)*invS;
        astr[i] = s;
    }
}

extern "C" void kernel_launch(void* const* d_in, const int* in_sizes, int n_in,
                              void* d_out, int out_size)
{
    const float* xt   = (const float*)d_in[0];
    const float* xd   = (const float*)d_in[1];
    // d_in[2] = x_known: unused by the reference computation
    const float* Wq   = (const float*)d_in[3];
    const float* Wk   = (const float*)d_in[4];
    const float* Wv   = (const float*)d_in[5];
    const float* lnqg = (const float*)d_in[6];
    const float* lnqb = (const float*)d_in[7];
    const float* lnkg = (const float*)d_in[8];
    const float* lnkb = (const float*)d_in[9];
    const float* Wr   = (const float*)d_in[10];
    const float* resb = (const float*)d_in[11];
    float* out  = (float*)d_out;
    float* attn = out + Bsz*Ln;   // context first, then attn (flattened tuple)

    cudaFuncSetAttribute(k4_flash, cudaFuncAttributeMaxDynamicSharedMemorySize, SMEM_K4);

    k1_ln_init<<<Bsz, 256>>>(xt, lnqg, lnqb, resb, out);
    k2_gemm<<<dim3(16,8,2), 256>>>(xt, Wq, Wr, out);
    k3_u<<<dim3(32,16), 128>>>(Wk, lnkg, lnkb);
    k4_flash<<<dim3(Bsz, NC), 128, SMEM_K4>>>(xd, attn);
    k5_reduce<<<dim3(Bsz, Hn), 128>>>(Wv, lnkg, lnkb, out, attn);
}

// round 17
// speedup vs baseline: 1.0818x; 1.0818x over previous
#include <cuda_runtime.h>
#include <math.h>

#define Bsz 64
#define Pn  2048
#define Ln  512
#define Hn  8
#define NC  16      // row-chunks per batch in flash pass
#define RPB (Pn/NC) // 128 rows per flash block
#define TR  8       // rows per smem stage

// k4 smem layout (bytes): x stages 2*16512, gu 16512, cf 2*256, scl 2*32, stats 2*128
#define XROW  2064              // padded row stride (bank offset 4 per row)
#define XSTG  (TR*XROW)         // 16512
#define OFF_GU  (2*XSTG)        // 33024
#define OFF_CF  (OFF_GU + Hn*XROW)   // 49536
#define OFF_SCL (OFF_CF + 2*64*4)    // 50048
#define OFF_ST  (OFF_SCL + 2*8*4)    // 50112  [slot][half][row][s1,s2]
#define SMEM_K4 (OFF_ST + 2*32*4)    // 50368

typedef unsigned long long u64;

// ---------------- static scratch (no allocation) ----------------
__device__ float  g_qn [Bsz*Ln];
__device__ float  g_Q  [Bsz*Ln];
__device__ __align__(16) float g_gu [Bsz*Hn*Ln];
__device__ float  g_Sgu[Bsz*Hn];
__device__ float  g_bu [Bsz*Hn];
__device__ float4 g_A4 [(size_t)Bsz*NC*Hn*(Ln/4)];   // partial accumulators
__device__ float4 g_msb[Bsz*NC*Hn];                  // (M, S, c, 0) per partial

// ---------------- packed f32x2 helpers ----------------
__device__ __forceinline__ u64 pk2(float lo, float hi) {
    u64 r; asm("mov.b64 %0, {%1,%2};" : "=l"(r) : "f"(lo), "f"(hi)); return r;
}
__device__ __forceinline__ void upk2(u64 v, float& lo, float& hi) {
    asm("mov.b64 {%0,%1}, %2;" : "=f"(lo), "=f"(hi) : "l"(v));
}
__device__ __forceinline__ u64 fma2(u64 a, u64 b, u64 c) {
    u64 r; asm("fma.rn.f32x2 %0, %1, %2, %3;" : "=l"(r) : "l"(a), "l"(b), "l"(c)); return r;
}
__device__ __forceinline__ u64 mul2(u64 a, u64 b) {
    u64 r; asm("mul.rn.f32x2 %0, %1, %2;" : "=l"(r) : "l"(a), "l"(b)); return r;
}
__device__ __forceinline__ u64 add2(u64 a, u64 b) {
    u64 r; asm("add.rn.f32x2 %0, %1, %2;" : "=l"(r) : "l"(a), "l"(b)); return r;
}

// ---------------- cp.async helpers ----------------
__device__ __forceinline__ void cpasync16(void* smem, const void* g) {
    unsigned s = (unsigned)__cvta_generic_to_shared(smem);
    asm volatile("cp.async.cg.shared.global [%0], [%1], 16;" :: "r"(s), "l"(g));
}
#define CP_COMMIT()  asm volatile("cp.async.commit_group;")
#define CP_WAIT(N)   asm volatile("cp.async.wait_group %0;" :: "n"(N))

// ---------------- K1: LN of query rows + init ----------------
__global__ void k1_ln_init(const float* __restrict__ xt,
                           const float* __restrict__ g, const float* __restrict__ b_,
                           const float* __restrict__ resb, float* __restrict__ outctx)
{
    int b = blockIdx.x, t = threadIdx.x;
    __shared__ float xs[Ln];
    __shared__ float red[16];
    __shared__ float stats[2];
    float2 v = ((const float2*)xt)[b*(Ln/2) + t];
    xs[2*t] = v.x; xs[2*t+1] = v.y;
    float s1 = v.x + v.y, s2 = v.x*v.x + v.y*v.y;
    #pragma unroll
    for (int o = 16; o; o >>= 1) {
        s1 += __shfl_xor_sync(~0u, s1, o);
        s2 += __shfl_xor_sync(~0u, s2, o);
    }
    int w = t >> 5, lane = t & 31;
    if (!lane) { red[w] = s1; red[8+w] = s2; }
    __syncthreads();
    if (!t) {
        float a = 0.f, c = 0.f;
        #pragma unroll
        for (int i = 0; i < 8; i++) { a += red[i]; c += red[8+i]; }
        float mean = a * (1.f/Ln);
        float var  = c * (1.f/Ln) - mean*mean;
        stats[0] = mean; stats[1] = rsqrtf(var + 1e-5f);
    }
    __syncthreads();
    float mean = stats[0], rstd = stats[1];
    #pragma unroll
    for (int l = t; l < Ln; l += 256) {
        g_qn[b*Ln + l]   = (xs[l] - mean) * rstd * g[l] + b_[l];
        outctx[b*Ln + l] = resb[l];
        g_Q[b*Ln + l]    = 0.f;
    }
    if (t < 8) { g_Sgu[b*8 + t] = 0.f; g_bu[b*8 + t] = 0.f; }
}

// ---------------- K2: split-K GEMMs: Q = qn@W_q ; out += x_trafic@res_W ----------------
__global__ void k2_gemm(const float* __restrict__ xt,
                        const float* __restrict__ Wq, const float* __restrict__ Wr,
                        float* __restrict__ outctx)
{
    int kc = blockIdx.x, bg = blockIdx.y, mat = blockIdx.z;
    const float* X = mat ? xt : g_qn;
    const float* W = mat ? Wr : Wq;
    float* OUT     = mat ? outctx : g_Q;
    __shared__ float xsm[8*64];
    int t = threadIdx.x;
    xsm[t]       = X[(bg*8 + (t>>6))*Ln       + kc*64 + (t&63)];
    xsm[t + 256] = X[(bg*8 + ((t+256)>>6))*Ln + kc*64 + (t&63)];
    __syncthreads();
    float acc[16];
    #pragma unroll
    for (int i = 0; i < 16; i++) acc[i] = 0.f;
    int d0 = t, d1 = t + 256;
    #pragma unroll 4
    for (int kk = 0; kk < 64; kk++) {
        float w0 = W[(kc*64 + kk)*Ln + d0];
        float w1 = W[(kc*64 + kk)*Ln + d1];
        #pragma unroll
        for (int bb = 0; bb < 8; bb++) {
            float x = xsm[bb*64 + kk];
            acc[2*bb]   += x * w0;
            acc[2*bb+1] += x * w1;
        }
    }
    #pragma unroll
    for (int bb = 0; bb < 8; bb++) {
        atomicAdd(&OUT[(bg*8+bb)*Ln + d0], acc[2*bb]);
        atomicAdd(&OUT[(bg*8+bb)*Ln + d1], acc[2*bb+1]);
    }
}

// ---------------- K3: tiled mini-GEMM  u[b,h,l] = (1/8) Wk_row(l,head h) . Q(b,head h) ----------------
__global__ void k3_u(const float* __restrict__ Wk,
                     const float* __restrict__ lng, const float* __restrict__ lnb)
{
    int lt = blockIdx.x, bg = blockIdx.y;
    int l0 = lt*16, b0 = bg*4;
    int t = threadIdx.x;
    int l = t & 15, h = t >> 4;
    __shared__ float4 Wks[16*128];
    __shared__ float4 Qs [4*128];

    const float4* wsrc = (const float4*)(Wk + (size_t)l0*Ln);
    #pragma unroll
    for (int k = 0; k < 16; k++) Wks[t + k*128] = wsrc[t + k*128];
    const float4* qsrc = (const float4*)(g_Q + (size_t)b0*Ln);
    #pragma unroll
    for (int k = 0; k < 4; k++) Qs[t + k*128] = qsrc[t + k*128];
    __syncthreads();

    float4 wr[16];
    #pragma unroll
    for (int k = 0; k < 16; k++) wr[k] = Wks[l*128 + h*16 + k];

    float gl = lng[l0 + l], bl = lnb[l0 + l];

    #pragma unroll
    for (int bb = 0; bb < 4; bb++) {
        float4 a4 = make_float4(0.f, 0.f, 0.f, 0.f);
        #pragma unroll
        for (int k = 0; k < 16; k++) {
            float4 q = Qs[bb*128 + h*16 + k];
            a4.x = fmaf(wr[k].x, q.x, a4.x);
            a4.y = fmaf(wr[k].y, q.y, a4.y);
            a4.z = fmaf(wr[k].z, q.z, a4.z);
            a4.w = fmaf(wr[k].w, q.w, a4.w);
        }
        float acc = (a4.x + a4.y) + (a4.z + a4.w);
        float u = acc * 0.125f;
        float guv = gl * u;
        g_gu[((size_t)(b0+bb)*Hn + h)*Ln + l0 + l] = guv;
        float sS = guv, sB = bl * u;
        #pragma unroll
        for (int o = 8; o; o >>= 1) {
            sS += __shfl_xor_sync(~0u, sS, o);
            sB += __shfl_xor_sync(~0u, sB, o);
        }
        if (l == 0) {
            atomicAdd(&g_Sgu[(b0+bb)*Hn + h], sS);
            atomicAdd(&g_bu [(b0+bb)*Hn + h], sB);
        }
    }
}

// ---------------- K4 v9: warp-specialized flash, B-computed stats (conflict-free) ----------------
// A-warps (vw 0,1): lane = (head_local, row); full-row DOT ONLY between barriers,
//                   score/softmax after barrier 2 using B-computed stats.
// B-warps (vw 2,3): conflict-free stats of tile T (sr=lane&7 -> 8 distinct rows per
//                   LDS phase) + accumulate tile T-1 + cp.async of T+1.
__global__ void __launch_bounds__(128, 4) k4_flash(
    const float* __restrict__ xd, float* __restrict__ attn_scores)
{
    extern __shared__ char sm[];
    int b = blockIdx.x, chunk = blockIdx.y;
    int t = threadIdx.x, w = t >> 5, lane = t & 31;
    int vw = (w + b + chunk) & 3;          // rotate roles across SMSPs
    const size_t rowbase = (size_t)b*Pn + (size_t)chunk*RPB;

    // ---- prologue: stage gu + x tile 0 ----
    {
        const char* gsrc = (const char*)(g_gu + (size_t)b*Hn*Ln);
        #pragma unroll
        for (int c = 0; c < 8; c++) {
            int idx = t + c*128;                  // 1024 chunks of 16B
            int h = idx >> 7, j = idx & 127;
            cpasync16(sm + OFF_GU + h*XROW + j*16, gsrc + idx*16);
        }
        const char* xsrc = (const char*)(xd + rowbase*Ln);
        #pragma unroll
        for (int c = 0; c < 8; c++) {
            int idx = t + c*128;
            int r = idx >> 7, j = idx & 127;
            cpasync16(sm + r*XROW + j*16, xsrc + idx*16);
        }
        CP_COMMIT();
        CP_WAIT(0);
    }

    // ---- per-role state ----
    int hl = lane >> 3, r = lane & 7;
    int h  = (vw & 1)*4 + hl;              // A: this lane's head
    int bw = vw - 2;                       // B: col-slice id (0/1)
    int sr = lane & 7, sq = lane >> 3;     // B stats: row (phase-distinct), quarter
    float Sgu_h = 0.f, bu_h = 0.f;
    const char* gurow = sm + OFF_GU + h*XROW;
    float* scout = attn_scores + ((size_t)b*Hn + h)*Pn + chunk*RPB;
    if (vw < 2) {
        Sgu_h = g_Sgu[b*Hn + h];
        bu_h  = g_bu [b*Hn + h];
    }
    float M = -1e30f, Sp = 0.f, cpart = 0.f;
    float dsum = 0.f;
    u64 acc[8][4];
    #pragma unroll
    for (int i = 0; i < 8; i++) { acc[i][0]=0ull; acc[i][1]=0ull; acc[i][2]=0ull; acc[i][3]=0ull; }

    __syncthreads();

    // ---- main loop ----
    for (int T = 0; T <= 16; T++) {
        if (vw >= 2) CP_WAIT(0);           // B's own group for x[T] (if any)
        __syncthreads();                   // B1: x[T] + cf[T-1] visible to all

        if (vw < 2) {
            if (T < 16) {                  // ---- A: dots only (4 chains) ----
                const ulonglong2* xp = (const ulonglong2*)(sm + (T&1)*XSTG + r*XROW);
                const ulonglong2* gp = (const ulonglong2*)gurow;
                u64 d0=0ull,d1=0ull,d2=0ull,d3=0ull;
                #pragma unroll 8
                for (int g = 0; g < 32; g++) {
                    ulonglong2 xv[4], gv[4];
                    #pragma unroll
                    for (int k = 0; k < 4; k++) { xv[k] = xp[g*4 + k]; gv[k] = gp[g*4 + k]; }
                    d0 = fma2(xv[0].x, gv[0].x, d0);
                    d1 = fma2(xv[0].y, gv[0].y, d1);
                    d2 = fma2(xv[1].x, gv[1].x, d2);
                    d3 = fma2(xv[1].y, gv[1].y, d3);
                    d0 = fma2(xv[2].x, gv[2].x, d0);
                    d1 = fma2(xv[2].y, gv[2].y, d1);
                    d2 = fma2(xv[3].x, gv[3].x, d2);
                    d3 = fma2(xv[3].y, gv[3].y, d3);
                }
                float lo, hi;
                upk2(add2(add2(d0,d1), add2(d2,d3)), lo, hi);
                dsum = lo + hi;
            }
        } else {
            if (T < 16) {                  // ---- B: stats of tile T, conflict-free mapping ----
                const ulonglong2* sp = (const ulonglong2*)(sm + (T&1)*XSTG + sr*XROW + bw*1024 + sq*256);
                u64 s1a=0ull,s1b=0ull,s2a=0ull,s2b=0ull;
                #pragma unroll
                for (int k = 0; k < 16; k++) {
                    ulonglong2 v = sp[k];
                    s1a = add2(s1a, v.x);
                    s1b = add2(s1b, v.y);
                    s2a = fma2(v.x, v.x, s2a);
                    s2b = fma2(v.y, v.y, s2b);
                }
                float lo, hi;
                upk2(add2(s1a,s1b), lo, hi); float s1 = lo + hi;
                upk2(add2(s2a,s2b), lo, hi); float s2 = lo + hi;
                // combine across the 4 quarter-lanes (lane xor 8, 16: same sr)
                s1 += __shfl_xor_sync(~0u, s1, 8);  s2 += __shfl_xor_sync(~0u, s2, 8);
                s1 += __shfl_xor_sync(~0u, s1, 16); s2 += __shfl_xor_sync(~0u, s2, 16);
                if (sq == 0) {
                    float* stp = (float*)(sm + OFF_ST) + (T&1)*32 + bw*16 + sr*2;
                    stp[0] = s1; stp[1] = s2;
                }
            }
            if (T >= 1) {                  // ---- B: accumulate tile T-1 ----
                int pm = (T-1) & 1;
                const float* cfp  = (const float*)(sm + OFF_CF) + pm*64;
                const float* sclp = (const float*)(sm + OFF_SCL) + pm*8;
                #pragma unroll
                for (int hh = 0; hh < 8; hh++) {
                    float sv = sclp[hh];
                    u64 s2v = pk2(sv, sv);
                    acc[hh][0]=mul2(acc[hh][0],s2v); acc[hh][1]=mul2(acc[hh][1],s2v);
                    acc[hh][2]=mul2(acc[hh][2],s2v); acc[hh][3]=mul2(acc[hh][3],s2v);
                }
                const char* xr0 = sm + pm*XSTG + bw*1024 + lane*32;
                #pragma unroll
                for (int rr = 0; rr < 8; rr++) {
                    ulonglong2 xa = *(const ulonglong2*)(xr0 + rr*XROW);
                    ulonglong2 xb = *(const ulonglong2*)(xr0 + rr*XROW + 16);
                    #pragma unroll
                    for (int hh = 0; hh < 8; hh++) {
                        float cfv = cfp[hh*8 + rr];
                        u64 c2 = pk2(cfv, cfv);
                        acc[hh][0] = fma2(c2, xa.x, acc[hh][0]);
                        acc[hh][1] = fma2(c2, xa.y, acc[hh][1]);
                        acc[hh][2] = fma2(c2, xb.x, acc[hh][2]);
                        acc[hh][3] = fma2(c2, xb.y, acc[hh][3]);
                    }
                }
            }
            if (T + 1 < 16) {   // ---- B: load x[T+1] into slot (T+1)&1 (this warp's slice just freed) ----
                const char* xsrc = (const char*)(xd + (rowbase + (size_t)(T+1)*TR)*Ln);
                char* dst = sm + ((T+1)&1)*XSTG + bw*1024 + lane*32;
                #pragma unroll
                for (int rr = 0; rr < 8; rr++) {
                    cpasync16(dst + rr*XROW,      xsrc + rr*2048 + bw*1024 + lane*32);
                    cpasync16(dst + rr*XROW + 16, xsrc + rr*2048 + bw*1024 + lane*32 + 16);
                }
                CP_COMMIT();
            }
        }

        __syncthreads();                   // B2: stats[T] visible to A

        if (vw < 2 && T < 16) {            // ---- A: score + softmax + cf store ----
            const float* stb = (const float*)(sm + OFF_ST) + (T&1)*32 + r*2;
            float s1 = stb[0] + stb[16];
            float s2 = stb[1] + stb[17];
            float mean = s1 * (1.f/Ln);
            float var  = s2 * (1.f/Ln) - mean*mean;
            float rstd = rsqrtf(var + 1e-5f);
            float score = rstd*(dsum - mean*Sgu_h) + bu_h;
            float m = score;
            m = fmaxf(m, __shfl_xor_sync(~0u, m, 1));
            m = fmaxf(m, __shfl_xor_sync(~0u, m, 2));
            m = fmaxf(m, __shfl_xor_sync(~0u, m, 4));
            float nM  = fmaxf(M, m);
            float scl = __expf(M - nM);
            float e   = __expf(score - nM);
            Sp = Sp*scl + e;
            float cfv = e * rstd;
            cpart = cpart*scl + cfv*mean;
            M = nM;
            ((float*)(sm + OFF_CF))[(T&1)*64 + h*8 + r] = cfv;
            if (r == 0) ((float*)(sm + OFF_SCL))[(T&1)*8 + h] = scl;
            scout[T*TR + r] = score;
        }
    }

    // ---- epilogue ----
    if (vw < 2) {
        float a0 = Sp, a1 = cpart;
        a0 += __shfl_xor_sync(~0u, a0, 1); a1 += __shfl_xor_sync(~0u, a1, 1);
        a0 += __shfl_xor_sync(~0u, a0, 2); a1 += __shfl_xor_sync(~0u, a1, 2);
        a0 += __shfl_xor_sync(~0u, a0, 4); a1 += __shfl_xor_sync(~0u, a1, 4);
        if (r == 0)
            g_msb[(b*NC + chunk)*Hn + h] = make_float4(M, a0, a1, 0.f);
    } else {
        size_t base = ((size_t)(b*NC + chunk)*Hn)*(Ln/4);
        #pragma unroll
        for (int hh = 0; hh < 8; hh++) {
            ulonglong2 v0; v0.x = acc[hh][0]; v0.y = acc[hh][1];
            ulonglong2 v1; v1.x = acc[hh][2]; v1.y = acc[hh][3];
            ulonglong2* dst = (ulonglong2*)&g_A4[base + (size_t)hh*(Ln/4) + bw*64 + lane*2];
            dst[0] = v0; dst[1] = v1;
        }
    }
}

// ---------------- K5: combine partials, ctx GEMV (ldg), AND normalize attn ----------------
__global__ void k5_reduce(const float* __restrict__ Wv,
                          const float* __restrict__ lng, const float* __restrict__ lnb,
                          float* __restrict__ outctx, float* __restrict__ attn)
{
    int b = blockIdx.x, h = blockIdx.y;
    int t = threadIdx.x;   // 128 threads
    __shared__ float wsh[NC];
    __shared__ float sInvS, sC, sMg;
    __shared__ float ws[Ln];
    __shared__ float part[128];
    if (t < 32) {          // parallel combine of the 16 partials (warp 0)
        int i = t & 15;
        float4 m = g_msb[(b*NC + i)*Hn + h];
        float Mg = m.x;
        #pragma unroll
        for (int o = 1; o < 16; o <<= 1) Mg = fmaxf(Mg, __shfl_xor_sync(~0u, Mg, o));
        Mg = fmaxf(Mg, __shfl_xor_sync(~0u, Mg, 16));   // full-warp uniform
        float wgt = __expf(m.x - Mg);
        if (t < 16) wsh[i] = wgt;
        float sg = wgt*m.y, cg = wgt*m.z;
        #pragma unroll
        for (int o = 1; o < 16; o <<= 1) {
            sg += __shfl_xor_sync(~0u, sg, o);
            cg += __shfl_xor_sync(~0u, cg, o);
        }
        if (t == 0) { sInvS = 1.f/sg; sC = cg; sMg = Mg; }
    }
    __syncthreads();
    float invS = sInvS, cg = sC, Mg = sMg;
    {
        int v = t;
        float4 acc = make_float4(0.f, 0.f, 0.f, 0.f);
        for (int i = 0; i < NC; i++) {
            float4 a = g_A4[((size_t)(b*NC+i)*Hn + h)*(Ln/4) + v];
            float wgt = wsh[i];
            acc.x += wgt*a.x; acc.y += wgt*a.y; acc.z += wgt*a.z; acc.w += wgt*a.w;
        }
        float4 g4 = ((const float4*)lng)[v], b4 = ((const float4*)lnb)[v];
        ws[4*v+0] = g4.x*(acc.x - cg)*invS + b4.x;
        ws[4*v+1] = g4.y*(acc.y - cg)*invS + b4.y;
        ws[4*v+2] = g4.z*(acc.z - cg)*invS + b4.z;
        ws[4*v+3] = g4.w*(acc.w - cg)*invS + b4.w;
    }
    __syncthreads();
    int d = t & 63, half = t >> 6;
    float acc = 0.f;
    #pragma unroll 8
    for (int l = half*256; l < half*256 + 256; l++)
        acc += ws[l] * __ldg(&Wv[l*Ln + h*64 + d]);
    part[t] = acc;
    __syncthreads();
    if (t < 64) outctx[b*Ln + h*64 + t] += part[t] + part[64 + t];

    float4* astr = (float4*)(attn + ((size_t)(b*Hn) + h)*Pn);
    #pragma unroll
    for (int rep = 0; rep < 4; rep++) {
        int i = t + rep*128;
        float4 s = astr[i];
        s.x = __expf(s.x - Mg)*invS;
        s.y = __expf(s.y - Mg)*invS;
        s.z = __expf(s.z - Mg)*invS;
        s.w = __expf(s.w - Mg)*invS;
        astr[i] = s;
    }
}

extern "C" void kernel_launch(void* const* d_in, const int* in_sizes, int n_in,
                              void* d_out, int out_size)
{
    const float* xt   = (const float*)d_in[0];
    const float* xd   = (const float*)d_in[1];
    // d_in[2] = x_known: unused by the reference computation
    const float* Wq   = (const float*)d_in[3];
    const float* Wk   = (const float*)d_in[4];
    const float* Wv   = (const float*)d_in[5];
    const float* lnqg = (const float*)d_in[6];
    const float* lnqb = (const float*)d_in[7];
    const float* lnkg = (const float*)d_in[8];
    const float* lnkb = (const float*)d_in[9];
    const float* Wr   = (const float*)d_in[10];
    const float* resb = (const float*)d_in[11];
    float* out  = (float*)d_out;
    float* attn = out + Bsz*Ln;   // context first, then attn (flattened tuple)

    cudaFuncSetAttribute(k4_flash, cudaFuncAttributeMaxDynamicSharedMemorySize, SMEM_K4);

    k1_ln_init<<<Bsz, 256>>>(xt, lnqg, lnqb, resb, out);
    k2_gemm<<<dim3(8,8,2), 256>>>(xt, Wq, Wr, out);
    k3_u<<<dim3(32,16), 128>>>(Wk, lnkg, lnkb);
    k4_flash<<<dim3(Bsz, NC), 128, SMEM_K4>>>(xd, attn);
    k5_reduce<<<dim3(Bsz, Hn), 128>>>(Wv, lnkg, lnkb, out, attn);
}